// round 8
// baseline (speedup 1.0000x reference)
#include <cuda_runtime.h>
#include <cuda_fp16.h>
#include <cstdint>

#define N_TOK 8192
#define DIM   1024
#define S_SEM 8192
#define L_LRN 128
#define NC    (S_SEM + L_LRN)   // 8320
#define NC_PAD 8448             // 33 * 256
#define NBLK  33                // 256-col blocks

// ---------------- device scratch ----------------
__device__ float g_xn[(size_t)N_TOK * DIM];
__device__ float g_cb[(size_t)NC * DIM];
__device__ __half g_ah[(size_t)N_TOK * DIM];
__device__ __half g_bh[(size_t)NC_PAD * DIM];   // rows >= NC remain zero
__device__ unsigned long long g_best[N_TOK];
__device__ unsigned long long g_blktop[(size_t)N_TOK * NBLK];

// ---------------- helpers ----------------
__device__ __forceinline__ unsigned int fkey(float f) {
    unsigned int u = __float_as_uint(f);
    return (u & 0x80000000u) ? ~u : (u | 0x80000000u);
}
__device__ __forceinline__ float fkey_inv(unsigned int k) {
    return __uint_as_float((k & 0x80000000u) ? (k ^ 0x80000000u) : ~k);
}
__device__ __forceinline__ uint32_t smem_u32(const void* p) {
    uint32_t a;
    asm("{ .reg .u64 t; cvta.to.shared.u64 t, %1; cvt.u32.u64 %0, t; }" : "=r"(a) : "l"(p));
    return a;
}
__device__ __forceinline__ void cp16(uint32_t dst, const void* src) {
    asm volatile("cp.async.cg.shared.global [%0], [%1], 16;" :: "r"(dst), "l"(src));
}
__device__ __forceinline__ void ldsm4(uint32_t* r, uint32_t addr) {
    asm volatile("ldmatrix.sync.aligned.m8n8.x4.shared.b16 {%0,%1,%2,%3}, [%4];"
        : "=r"(r[0]), "=r"(r[1]), "=r"(r[2]), "=r"(r[3]) : "r"(addr));
}
__device__ __forceinline__ void mma16816(float* c, const uint32_t* a,
                                         uint32_t b0, uint32_t b1) {
    asm volatile(
        "mma.sync.aligned.m16n8k16.row.col.f32.f16.f16.f32 "
        "{%0,%1,%2,%3}, {%4,%5,%6,%7}, {%8,%9}, {%0,%1,%2,%3};"
        : "+f"(c[0]), "+f"(c[1]), "+f"(c[2]), "+f"(c[3])
        : "r"(a[0]), "r"(a[1]), "r"(a[2]), "r"(a[3]), "r"(b0), "r"(b1));
}

// ---------------- normalize + fp16 convert ----------------
__global__ void normalize_kernel(const float* __restrict__ src, int mode) {
    int row = blockIdx.x;
    int tid = threadIdx.x;

    float4 v = ((const float4*)(src + (size_t)row * DIM))[tid];
    float ss = v.x * v.x + v.y * v.y + v.z * v.z + v.w * v.w;
    #pragma unroll
    for (int off = 16; off > 0; off >>= 1) ss += __shfl_down_sync(0xffffffffu, ss, off);

    __shared__ float ws[8];
    __shared__ float s_scale;
    int lane = tid & 31, wid = tid >> 5;
    if (lane == 0) ws[wid] = ss;
    __syncthreads();
    if (tid == 0) {
        float t = 0.f;
        #pragma unroll
        for (int i = 0; i < 8; i++) t += ws[i];
        s_scale = 1.0f / fmaxf(sqrtf(t), 1e-8f);
    }
    __syncthreads();
    float sc = s_scale;
    float4 o = make_float4(v.x * sc, v.y * sc, v.z * sc, v.w * sc);

    size_t orow = (mode == 2) ? (size_t)(S_SEM + row) : (size_t)row;
    float* fdst = (mode == 0) ? g_xn : g_cb;
    ((float4*)(fdst + orow * DIM))[tid] = o;

    __half2 h0 = make_half2(__float2half_rn(o.x), __float2half_rn(o.y));
    __half2 h1 = make_half2(__float2half_rn(o.z), __float2half_rn(o.w));
    __half* hdst = (mode == 0) ? g_ah : g_bh;
    ((uint2*)(hdst + orow * DIM))[tid] = make_uint2(*(uint32_t*)&h0, *(uint32_t*)&h1);

    // fold blktop zeroing into mode-0 pass
    if (mode == 0 && tid < NBLK) g_blktop[(size_t)row * NBLK + tid] = 0ull;
}

// ---------------- fp16 mma GEMM (BM=128, BN=256, BK=64, 3 stages, 1 sync/tile) ----------------
#define BM 128
#define BN 256
#define BK 64
#define STAGES 3
#define PADB 144                          // bytes per row (64 halves = 128B + 16B pad)
#define OFF_A 0
#define OFF_B (128 * PADB)                // 18432
#define STG_BYTES ((128 + 256) * PADB)    // 55296
#define KT2 (DIM / BK)                    // 16
#define SMEM_TOTAL (STAGES * STG_BYTES)   // 165888

__device__ __forceinline__ void load_stage(uint32_t st, int tid, int kt,
                                           size_t rowA0, size_t rowB0) {
    // A: 128 rows x 8 chunks(16B) = 1024; 4 per thread
    #pragma unroll
    for (int i = 0; i < 4; i++) {
        int idx = tid + i * 256;
        int r = idx >> 3, ch = idx & 7;
        cp16(st + OFF_A + (uint32_t)(r * PADB + ch * 16),
             g_ah + (rowA0 + r) * DIM + kt + ch * 8);
    }
    // B: 256 rows x 8 chunks = 2048; 8 per thread
    #pragma unroll
    for (int i = 0; i < 8; i++) {
        int idx = tid + i * 256;
        int r = idx >> 3, ch = idx & 7;
        cp16(st + OFF_B + (uint32_t)(r * PADB + ch * 16),
             g_bh + (rowB0 + r) * DIM + kt + ch * 8);
    }
    asm volatile("cp.async.commit_group;" ::: "memory");
}

__global__ __launch_bounds__(256, 1)
void gemm_mma_kernel(float* __restrict__ C) {
    extern __shared__ char smem[];
    const uint32_t sb = smem_u32(smem);
    const int tid = threadIdx.x;
    const int lane = tid & 31;
    const int w = tid >> 5;
    const int warp_m = w >> 2;   // 0..1 (64 rows)
    const int warp_n = w & 3;    // 0..3 (64 cols)
    const int bm = blockIdx.y;
    const int bn = blockIdx.x;   // 0..32

    const size_t rowA0 = (size_t)bm * BM;
    const size_t rowB0 = (size_t)bn * BN;

    float c[4][8][4];
    #pragma unroll
    for (int mi = 0; mi < 4; mi++)
        #pragma unroll
        for (int ni = 0; ni < 8; ni++)
            #pragma unroll
            for (int j = 0; j < 4; j++) c[mi][ni][j] = 0.f;

    load_stage(sb + 0 * STG_BYTES, tid, 0, rowA0, rowB0);
    load_stage(sb + 1 * STG_BYTES, tid, BK, rowA0, rowB0);

    const uint32_t aBase = sb + OFF_A +
        (uint32_t)(warp_m * 64 + (lane & 15)) * PADB + ((lane >> 4) << 4);
    const uint32_t bBase = sb + OFF_B +
        (uint32_t)(warp_n * 64 + (lane & 15)) * PADB + ((lane >> 4) << 4);

    uint32_t af0[4][4], bf0[4][4], af1[4][4], bf1[4][4];

    asm volatile("cp.async.wait_group 1;" ::: "memory");
    __syncthreads();

    // preload tile0 ks0
    #pragma unroll
    for (int mi = 0; mi < 4; mi++) ldsm4(af0[mi], aBase + (uint32_t)(mi * 16) * PADB);
    #pragma unroll
    for (int p = 0; p < 4; p++)  ldsm4(bf0[p], bBase + (uint32_t)(p * 16) * PADB);

    #define MMA_BLOCK(AF, BF)                                              \
        _Pragma("unroll")                                                  \
        for (int mi = 0; mi < 4; mi++)                                     \
            _Pragma("unroll")                                              \
            for (int p = 0; p < 4; p++) {                                  \
                mma16816(c[mi][2 * p + 0], AF[mi], BF[p][0], BF[p][2]);    \
                mma16816(c[mi][2 * p + 1], AF[mi], BF[p][1], BF[p][3]);    \
            }

    #define LDSM_PHASE(AF, BF, SO, KB)                                             \
        _Pragma("unroll")                                                          \
        for (int mi = 0; mi < 4; mi++)                                             \
            ldsm4(AF[mi], aBase + (SO) + (uint32_t)(mi * 16) * PADB + (KB));       \
        _Pragma("unroll")                                                          \
        for (int p = 0; p < 4; p++)                                                \
            ldsm4(BF[p], bBase + (SO) + (uint32_t)(p * 16) * PADB + (KB));

    for (int it = 0; it < KT2; it++) {
        const uint32_t so = (uint32_t)((it % 3) * STG_BYTES);

        LDSM_PHASE(af1, bf1, so, 32);   // ks1
        MMA_BLOCK(af0, bf0);            // ks0
        LDSM_PHASE(af0, bf0, so, 64);   // ks2
        MMA_BLOCK(af1, bf1);            // ks1
        LDSM_PHASE(af1, bf1, so, 96);   // ks3
        MMA_BLOCK(af0, bf0);            // ks2

        if (it + 2 < KT2)
            load_stage(sb + ((it + 2) % 3) * STG_BYTES, tid, (it + 2) * BK, rowA0, rowB0);
        else
            asm volatile("cp.async.commit_group;" ::: "memory");

        asm volatile("cp.async.wait_group 1;" ::: "memory");
        __syncthreads();

        if (it + 1 < KT2) {
            const uint32_t so2 = (uint32_t)(((it + 1) % 3) * STG_BYTES);
            LDSM_PHASE(af0, bf0, so2, 0);   // next tile ks0
        }
        MMA_BLOCK(af1, bf1);            // ks3
    }

    // ---------------- epilogue: store + per-(row, block) top key ----------------
    const int g = lane >> 2, q = lane & 3;
    #pragma unroll
    for (int mi = 0; mi < 4; mi++) {
        #pragma unroll
        for (int half = 0; half < 2; half++) {
            const int row = bm * BM + warp_m * 64 + mi * 16 + g + half * 8;
            float* crow = C + (size_t)row * NC;
            unsigned long long key = 0ull;
            #pragma unroll
            for (int ni = 0; ni < 8; ni++) {
                int col0 = bn * BN + warp_n * 64 + ni * 8 + q * 2;
                if (col0 < NC) {
                    float v0 = c[mi][ni][half * 2 + 0];
                    float v1 = c[mi][ni][half * 2 + 1];
                    unsigned long long k0 = ((unsigned long long)fkey(v0) << 32) |
                                            (unsigned int)(~(unsigned int)col0);
                    unsigned long long k1 = ((unsigned long long)fkey(v1) << 32) |
                                            (unsigned int)(~(unsigned int)(col0 + 1));
                    key = (k0 > key) ? k0 : key;
                    key = (k1 > key) ? k1 : key;
                    *(float2*)(crow + col0) = make_float2(v0, v1);
                }
            }
            unsigned long long o1 = __shfl_xor_sync(0xffffffffu, key, 1);
            key = (o1 > key) ? o1 : key;
            unsigned long long o2 = __shfl_xor_sync(0xffffffffu, key, 2);
            key = (o2 > key) ? o2 : key;
            if (q == 0) atomicMax(&g_blktop[(size_t)row * NBLK + bn], key);
        }
    }
}

// ---------------- rescue + gather (fused) ----------------
#define RESCUE_WIN 3e-4f
#define RESCUE_CAP 64

__global__ void rescue_gather_kernel(const float* __restrict__ C,
                                     float* __restrict__ idx_out,
                                     float* __restrict__ zq,
                                     float* __restrict__ zqst) {
    const int row = blockIdx.x;
    const int tid = threadIdx.x;
    __shared__ unsigned long long s_keys[NBLK];
    __shared__ unsigned long long s_kmax;
    __shared__ int s_cnt;
    __shared__ int s_idx[RESCUE_CAP];
    __shared__ float s_red[256];
    __shared__ unsigned long long s_best;
    __shared__ unsigned long long s_fin;

    if (tid < NBLK) s_keys[tid] = g_blktop[(size_t)row * NBLK + tid];
    if (tid == 0) { s_cnt = 0; s_best = 0ull; }
    __syncthreads();
    if (tid == 0) {
        unsigned long long m = 0ull;
        #pragma unroll
        for (int b = 0; b < NBLK; b++) m = (s_keys[b] > m) ? s_keys[b] : m;
        s_kmax = m;
    }
    __syncthreads();

    const unsigned long long kmax = s_kmax;
    const float amax = fkey_inv((unsigned int)(kmax >> 32));
    const float thresh = amax - RESCUE_WIN;
    const unsigned long long kthresh = ((unsigned long long)fkey(thresh) << 32);

    const float* rowp = C + (size_t)row * NC;
    for (int b = 0; b < NBLK; b++) {
        if (s_keys[b] >= kthresh) {
            int col = b * 256 + tid;
            if (col < NC) {
                float v = rowp[col];
                if (v > thresh) {
                    int p = atomicAdd(&s_cnt, 1);
                    if (p < RESCUE_CAP) s_idx[p] = col;
                }
            }
        }
    }
    __syncthreads();
    int cnt = s_cnt < RESCUE_CAP ? s_cnt : RESCUE_CAP;

    if (cnt <= 1) {
        if (tid == 0) { g_best[row] = kmax; s_fin = kmax; }
    } else {
        const float* xr = g_xn + (size_t)row * DIM;
        for (int ci = 0; ci < cnt; ci++) {
            int idx = s_idx[ci];
            const float* cbr = g_cb + (size_t)idx * DIM;
            float p = 0.f;
            #pragma unroll
            for (int e = 0; e < 4; e++) p += xr[tid * 4 + e] * cbr[tid * 4 + e];
            s_red[tid] = p;
            __syncthreads();
            for (int s = 128; s > 0; s >>= 1) {
                if (tid < s) s_red[tid] += s_red[tid + s];
                __syncthreads();
            }
            if (tid == 0) {
                unsigned long long key = ((unsigned long long)fkey(s_red[0]) << 32) |
                                         (unsigned int)(~(unsigned int)idx);
                if (key > s_best) s_best = key;
            }
            __syncthreads();
        }
        if (tid == 0) { g_best[row] = s_best; s_fin = s_best; }
    }
    __syncthreads();

    // fused gather
    const unsigned int idx = ~(unsigned int)(s_fin & 0xffffffffu);
    if (tid == 0) idx_out[row] = (float)idx;
    float4 v = ((const float4*)(g_cb + (size_t)idx * DIM))[tid];
    ((float4*)(zq   + (size_t)row * DIM))[tid] = v;
    ((float4*)(zqst + (size_t)row * DIM))[tid] = v;
}

// ---------------- losses ----------------
__global__ void loss_kernel(float* __restrict__ out3) {
    __shared__ float s_c[256], s_v[256], s_n[256];
    int tid = threadIdx.x;
    float c = 0.f, v = 0.f, n = 0.f;
    for (int r = tid; r < N_TOK; r += 256) {
        unsigned long long k = g_best[r];
        unsigned int idx = ~(unsigned int)(k & 0xffffffffu);
        float val = fkey_inv((unsigned int)(k >> 32));
        float d = 1.0f - val;
        c += d;
        if (idx >= S_SEM) { v += d; n += 1.0f; }
    }
    s_c[tid] = c; s_v[tid] = v; s_n[tid] = n;
    __syncthreads();
    for (int s = 128; s > 0; s >>= 1) {
        if (tid < s) {
            s_c[tid] += s_c[tid + s];
            s_v[tid] += s_v[tid + s];
            s_n[tid] += s_n[tid + s];
        }
        __syncthreads();
    }
    if (tid == 0) {
        float commit = s_c[0] / (float)N_TOK;
        float vq = s_v[0] / (s_n[0] + 1e-6f);
        out3[0] = vq;
        out3[1] = commit;
        out3[2] = vq + 0.25f * commit;
    }
}

// ---------------- launch ----------------
extern "C" void kernel_launch(void* const* d_in, const int* in_sizes, int n_in,
                              void* d_out, int out_size) {
    const float* x   = (const float*)d_in[0];
    const float* sem = (const float*)d_in[1];
    const float* lrn = (const float*)d_in[2];
    float* out = (float*)d_out;

    float* logits = out;
    float* idxf   = logits + (size_t)N_TOK * NC;
    float* zq     = idxf + N_TOK;
    float* zqst   = zq + (size_t)N_TOK * DIM;
    float* sc3    = zqst + (size_t)N_TOK * DIM;

    cudaFuncSetAttribute(gemm_mma_kernel,
                         cudaFuncAttributeMaxDynamicSharedMemorySize, SMEM_TOTAL);

    normalize_kernel<<<N_TOK, 256>>>(x, 0);
    normalize_kernel<<<S_SEM, 256>>>(sem, 1);
    normalize_kernel<<<L_LRN, 256>>>(lrn, 2);

    dim3 grid(NC_PAD / BN, N_TOK / BM);   // (33, 64)
    gemm_mma_kernel<<<grid, 256, SMEM_TOTAL>>>(logits);

    rescue_gather_kernel<<<N_TOK, 256>>>(logits, idxf, zq, zqst);
    loss_kernel<<<1, 256>>>(sc3);
}

// round 9
// speedup vs baseline: 1.0709x; 1.0709x over previous
#include <cuda_runtime.h>
#include <cuda_fp16.h>
#include <cstdint>

#define N_TOK 8192
#define DIM   1024
#define S_SEM 8192
#define L_LRN 128
#define NC    (S_SEM + L_LRN)   // 8320
#define NC_PAD 8448             // 33 * 256
#define NBLK  33                // 256-col blocks

// ---------------- device scratch ----------------
__device__ float g_xn[(size_t)N_TOK * DIM];
__device__ float g_cb[(size_t)NC * DIM];
__device__ __half g_ah[(size_t)N_TOK * DIM];
__device__ __half g_bh[(size_t)NC_PAD * DIM];   // rows >= NC remain zero
__device__ unsigned long long g_best[N_TOK];
__device__ unsigned long long g_blktop[(size_t)N_TOK * NBLK];

// ---------------- helpers ----------------
__device__ __forceinline__ unsigned int fkey(float f) {
    unsigned int u = __float_as_uint(f);
    return (u & 0x80000000u) ? ~u : (u | 0x80000000u);
}
__device__ __forceinline__ float fkey_inv(unsigned int k) {
    return __uint_as_float((k & 0x80000000u) ? (k ^ 0x80000000u) : ~k);
}
__device__ __forceinline__ uint32_t smem_u32(const void* p) {
    uint32_t a;
    asm("{ .reg .u64 t; cvta.to.shared.u64 t, %1; cvt.u32.u64 %0, t; }" : "=r"(a) : "l"(p));
    return a;
}
__device__ __forceinline__ void cp16(uint32_t dst, const void* src) {
    asm volatile("cp.async.cg.shared.global [%0], [%1], 16;" :: "r"(dst), "l"(src));
}
__device__ __forceinline__ void ldsm4(uint32_t* r, uint32_t addr) {
    asm volatile("ldmatrix.sync.aligned.m8n8.x4.shared.b16 {%0,%1,%2,%3}, [%4];"
        : "=r"(r[0]), "=r"(r[1]), "=r"(r[2]), "=r"(r[3]) : "r"(addr));
}
__device__ __forceinline__ void mma16816(float* c, const uint32_t* a,
                                         uint32_t b0, uint32_t b1) {
    asm volatile(
        "mma.sync.aligned.m16n8k16.row.col.f32.f16.f16.f32 "
        "{%0,%1,%2,%3}, {%4,%5,%6,%7}, {%8,%9}, {%0,%1,%2,%3};"
        : "+f"(c[0]), "+f"(c[1]), "+f"(c[2]), "+f"(c[3])
        : "r"(a[0]), "r"(a[1]), "r"(a[2]), "r"(a[3]), "r"(b0), "r"(b1));
}

// ---------------- normalize + fp16 convert ----------------
__global__ void normalize_kernel(const float* __restrict__ src, int mode) {
    int row = blockIdx.x;
    int tid = threadIdx.x;

    float4 v = ((const float4*)(src + (size_t)row * DIM))[tid];
    float ss = v.x * v.x + v.y * v.y + v.z * v.z + v.w * v.w;
    #pragma unroll
    for (int off = 16; off > 0; off >>= 1) ss += __shfl_down_sync(0xffffffffu, ss, off);

    __shared__ float ws[8];
    __shared__ float s_scale;
    int lane = tid & 31, wid = tid >> 5;
    if (lane == 0) ws[wid] = ss;
    __syncthreads();
    if (tid == 0) {
        float t = 0.f;
        #pragma unroll
        for (int i = 0; i < 8; i++) t += ws[i];
        s_scale = 1.0f / fmaxf(sqrtf(t), 1e-8f);
    }
    __syncthreads();
    float sc = s_scale;
    float4 o = make_float4(v.x * sc, v.y * sc, v.z * sc, v.w * sc);

    size_t orow = (mode == 2) ? (size_t)(S_SEM + row) : (size_t)row;
    float* fdst = (mode == 0) ? g_xn : g_cb;
    ((float4*)(fdst + orow * DIM))[tid] = o;

    __half2 h0 = make_half2(__float2half_rn(o.x), __float2half_rn(o.y));
    __half2 h1 = make_half2(__float2half_rn(o.z), __float2half_rn(o.w));
    __half* hdst = (mode == 0) ? g_ah : g_bh;
    ((uint2*)(hdst + orow * DIM))[tid] = make_uint2(*(uint32_t*)&h0, *(uint32_t*)&h1);

    // fold blktop zeroing into mode-0 pass
    if (mode == 0 && tid < NBLK) g_blktop[(size_t)row * NBLK + tid] = 0ull;
}

// ---------------- fp16 mma GEMM (BM=128, BN=256, 256 threads, frag dbl-buffer) ----------------
#define BM 128
#define BN 256
#define BK 32
#define STAGES 4
#define PAD 40
#define PADB (PAD * 2)
#define OFF_A 0
#define OFF_B (128 * PADB)
#define STG_BYTES ((128 + 256) * PADB)   // 30720
#define KTILES (DIM / BK)                // 32
#define SMEM_TOTAL (STAGES * STG_BYTES)  // 122880

__device__ __forceinline__ void load_stage(uint32_t st, int tid, int kt,
                                           size_t rowA0, size_t rowB0) {
    #pragma unroll
    for (int i = 0; i < 2; i++) {
        int idx = tid + i * 256;
        int r = idx >> 2, ch = idx & 3;
        cp16(st + OFF_A + (uint32_t)(r * PADB + ch * 16),
             g_ah + (rowA0 + r) * DIM + kt + ch * 8);
    }
    #pragma unroll
    for (int i = 0; i < 4; i++) {
        int idx = tid + i * 256;
        int r = idx >> 2, ch = idx & 3;
        cp16(st + OFF_B + (uint32_t)(r * PADB + ch * 16),
             g_bh + (rowB0 + r) * DIM + kt + ch * 8);
    }
    asm volatile("cp.async.commit_group;" ::: "memory");
}

__global__ __launch_bounds__(256, 1)
void gemm_mma_kernel(float* __restrict__ C) {
    extern __shared__ char smem[];
    const uint32_t sb = smem_u32(smem);
    const int tid = threadIdx.x;
    const int lane = tid & 31;
    const int w = tid >> 5;
    const int warp_m = w >> 2;   // 0..1 (64 rows)
    const int warp_n = w & 3;    // 0..3 (64 cols)
    const int bm = blockIdx.y;
    const int bn = blockIdx.x;   // 0..32

    const size_t rowA0 = (size_t)bm * BM;
    const size_t rowB0 = (size_t)bn * BN;

    float c[4][8][4];
    #pragma unroll
    for (int mi = 0; mi < 4; mi++)
        #pragma unroll
        for (int ni = 0; ni < 8; ni++)
            #pragma unroll
            for (int j = 0; j < 4; j++) c[mi][ni][j] = 0.f;

    #pragma unroll
    for (int s = 0; s < 3; s++)
        load_stage(sb + s * STG_BYTES, tid, s * BK, rowA0, rowB0);

    const uint32_t aBase = sb + OFF_A +
        (uint32_t)(warp_m * 64 + (lane & 15)) * PADB + ((lane >> 4) << 4);
    const uint32_t bBase = sb + OFF_B +
        (uint32_t)(warp_n * 64 + (lane & 15)) * PADB + ((lane >> 4) << 4);

    uint32_t af0[4][4], bf0[4][4], af1[4][4], bf1[4][4];

    asm volatile("cp.async.wait_group 2;" ::: "memory");
    __syncthreads();

    // preload frags: tile 0, ks 0
    #pragma unroll
    for (int mi = 0; mi < 4; mi++) ldsm4(af0[mi], aBase + (uint32_t)(mi * 16) * PADB);
    #pragma unroll
    for (int p = 0; p < 4; p++)  ldsm4(bf0[p], bBase + (uint32_t)(p * 16) * PADB);

    for (int it = 0; it < KTILES; it++) {
        const uint32_t so = (uint32_t)((it & 3) * STG_BYTES);

        // prefetch ks=1 frags of this tile
        #pragma unroll
        for (int mi = 0; mi < 4; mi++)
            ldsm4(af1[mi], aBase + so + (uint32_t)(mi * 16) * PADB + 32);
        #pragma unroll
        for (int p = 0; p < 4; p++)
            ldsm4(bf1[p], bBase + so + (uint32_t)(p * 16) * PADB + 32);

        // MMAs on ks=0 frags
        #pragma unroll
        for (int mi = 0; mi < 4; mi++)
            #pragma unroll
            for (int p = 0; p < 4; p++) {
                mma16816(c[mi][2 * p + 0], af0[mi], bf0[p][0], bf0[p][2]);
                mma16816(c[mi][2 * p + 1], af0[mi], bf0[p][1], bf0[p][3]);
            }

        if (it + 3 < KTILES)
            load_stage(sb + ((it + 3) & 3) * STG_BYTES, tid, (it + 3) * BK, rowA0, rowB0);
        else
            asm volatile("cp.async.commit_group;" ::: "memory");

        asm volatile("cp.async.wait_group 2;" ::: "memory");
        __syncthreads();

        // prefetch ks=0 frags of next tile
        if (it + 1 < KTILES) {
            const uint32_t so2 = (uint32_t)(((it + 1) & 3) * STG_BYTES);
            #pragma unroll
            for (int mi = 0; mi < 4; mi++)
                ldsm4(af0[mi], aBase + so2 + (uint32_t)(mi * 16) * PADB);
            #pragma unroll
            for (int p = 0; p < 4; p++)
                ldsm4(bf0[p], bBase + so2 + (uint32_t)(p * 16) * PADB);
        }

        // MMAs on ks=1 frags
        #pragma unroll
        for (int mi = 0; mi < 4; mi++)
            #pragma unroll
            for (int p = 0; p < 4; p++) {
                mma16816(c[mi][2 * p + 0], af1[mi], bf1[p][0], bf1[p][2]);
                mma16816(c[mi][2 * p + 1], af1[mi], bf1[p][1], bf1[p][3]);
            }
    }

    // ---------------- epilogue: store + per-(row, block) top key ----------------
    const int g = lane >> 2, q = lane & 3;
    #pragma unroll
    for (int mi = 0; mi < 4; mi++) {
        #pragma unroll
        for (int half = 0; half < 2; half++) {
            const int row = bm * BM + warp_m * 64 + mi * 16 + g + half * 8;
            float* crow = C + (size_t)row * NC;
            unsigned long long key = 0ull;
            #pragma unroll
            for (int ni = 0; ni < 8; ni++) {
                int col0 = bn * BN + warp_n * 64 + ni * 8 + q * 2;
                if (col0 < NC) {
                    float v0 = c[mi][ni][half * 2 + 0];
                    float v1 = c[mi][ni][half * 2 + 1];
                    unsigned long long k0 = ((unsigned long long)fkey(v0) << 32) |
                                            (unsigned int)(~(unsigned int)col0);
                    unsigned long long k1 = ((unsigned long long)fkey(v1) << 32) |
                                            (unsigned int)(~(unsigned int)(col0 + 1));
                    key = (k0 > key) ? k0 : key;
                    key = (k1 > key) ? k1 : key;
                    *(float2*)(crow + col0) = make_float2(v0, v1);
                }
            }
            unsigned long long o1 = __shfl_xor_sync(0xffffffffu, key, 1);
            key = (o1 > key) ? o1 : key;
            unsigned long long o2 = __shfl_xor_sync(0xffffffffu, key, 2);
            key = (o2 > key) ? o2 : key;
            if (q == 0) atomicMax(&g_blktop[(size_t)row * NBLK + bn], key);
        }
    }
}

// ---------------- rescue + gather (fused) ----------------
#define RESCUE_WIN 3e-4f
#define RESCUE_CAP 64

__global__ void rescue_gather_kernel(const float* __restrict__ C,
                                     float* __restrict__ idx_out,
                                     float* __restrict__ zq,
                                     float* __restrict__ zqst) {
    const int row = blockIdx.x;
    const int tid = threadIdx.x;
    __shared__ unsigned long long s_keys[NBLK];
    __shared__ unsigned long long s_kmax;
    __shared__ int s_cnt;
    __shared__ int s_idx[RESCUE_CAP];
    __shared__ float s_red[256];
    __shared__ unsigned long long s_best;
    __shared__ unsigned long long s_fin;

    if (tid < NBLK) s_keys[tid] = g_blktop[(size_t)row * NBLK + tid];
    if (tid == 0) { s_cnt = 0; s_best = 0ull; }
    __syncthreads();
    if (tid == 0) {
        unsigned long long m = 0ull;
        #pragma unroll
        for (int b = 0; b < NBLK; b++) m = (s_keys[b] > m) ? s_keys[b] : m;
        s_kmax = m;
    }
    __syncthreads();

    const unsigned long long kmax = s_kmax;
    const float amax = fkey_inv((unsigned int)(kmax >> 32));
    const float thresh = amax - RESCUE_WIN;
    const unsigned long long kthresh = ((unsigned long long)fkey(thresh) << 32);

    const float* rowp = C + (size_t)row * NC;
    for (int b = 0; b < NBLK; b++) {
        if (s_keys[b] >= kthresh) {
            int col = b * 256 + tid;
            if (col < NC) {
                float v = rowp[col];
                if (v > thresh) {
                    int p = atomicAdd(&s_cnt, 1);
                    if (p < RESCUE_CAP) s_idx[p] = col;
                }
            }
        }
    }
    __syncthreads();
    int cnt = s_cnt < RESCUE_CAP ? s_cnt : RESCUE_CAP;

    if (cnt <= 1) {
        if (tid == 0) { g_best[row] = kmax; s_fin = kmax; }
    } else {
        const float* xr = g_xn + (size_t)row * DIM;
        for (int ci = 0; ci < cnt; ci++) {
            int idx = s_idx[ci];
            const float* cbr = g_cb + (size_t)idx * DIM;
            float p = 0.f;
            #pragma unroll
            for (int e = 0; e < 4; e++) p += xr[tid * 4 + e] * cbr[tid * 4 + e];
            s_red[tid] = p;
            __syncthreads();
            for (int s = 128; s > 0; s >>= 1) {
                if (tid < s) s_red[tid] += s_red[tid + s];
                __syncthreads();
            }
            if (tid == 0) {
                unsigned long long key = ((unsigned long long)fkey(s_red[0]) << 32) |
                                         (unsigned int)(~(unsigned int)idx);
                if (key > s_best) s_best = key;
            }
            __syncthreads();
        }
        if (tid == 0) { g_best[row] = s_best; s_fin = s_best; }
    }
    __syncthreads();

    // fused gather
    const unsigned int idx = ~(unsigned int)(s_fin & 0xffffffffu);
    if (tid == 0) idx_out[row] = (float)idx;
    float4 v = ((const float4*)(g_cb + (size_t)idx * DIM))[tid];
    ((float4*)(zq   + (size_t)row * DIM))[tid] = v;
    ((float4*)(zqst + (size_t)row * DIM))[tid] = v;
}

// ---------------- losses ----------------
__global__ void loss_kernel(float* __restrict__ out3) {
    __shared__ float s_c[256], s_v[256], s_n[256];
    int tid = threadIdx.x;
    float c = 0.f, v = 0.f, n = 0.f;
    for (int r = tid; r < N_TOK; r += 256) {
        unsigned long long k = g_best[r];
        unsigned int idx = ~(unsigned int)(k & 0xffffffffu);
        float val = fkey_inv((unsigned int)(k >> 32));
        float d = 1.0f - val;
        c += d;
        if (idx >= S_SEM) { v += d; n += 1.0f; }
    }
    s_c[tid] = c; s_v[tid] = v; s_n[tid] = n;
    __syncthreads();
    for (int s = 128; s > 0; s >>= 1) {
        if (tid < s) {
            s_c[tid] += s_c[tid + s];
            s_v[tid] += s_v[tid + s];
            s_n[tid] += s_n[tid + s];
        }
        __syncthreads();
    }
    if (tid == 0) {
        float commit = s_c[0] / (float)N_TOK;
        float vq = s_v[0] / (s_n[0] + 1e-6f);
        out3[0] = vq;
        out3[1] = commit;
        out3[2] = vq + 0.25f * commit;
    }
}

// ---------------- launch ----------------
extern "C" void kernel_launch(void* const* d_in, const int* in_sizes, int n_in,
                              void* d_out, int out_size) {
    const float* x   = (const float*)d_in[0];
    const float* sem = (const float*)d_in[1];
    const float* lrn = (const float*)d_in[2];
    float* out = (float*)d_out;

    float* logits = out;
    float* idxf   = logits + (size_t)N_TOK * NC;
    float* zq     = idxf + N_TOK;
    float* zqst   = zq + (size_t)N_TOK * DIM;
    float* sc3    = zqst + (size_t)N_TOK * DIM;

    cudaFuncSetAttribute(gemm_mma_kernel,
                         cudaFuncAttributeMaxDynamicSharedMemorySize, SMEM_TOTAL);

    normalize_kernel<<<N_TOK, 256>>>(x, 0);
    normalize_kernel<<<S_SEM, 256>>>(sem, 1);
    normalize_kernel<<<L_LRN, 256>>>(lrn, 2);

    dim3 grid(NC_PAD / BN, N_TOK / BM);   // (33, 64)
    gemm_mma_kernel<<<grid, 256, SMEM_TOTAL>>>(logits);

    rescue_gather_kernel<<<N_TOK, 256>>>(logits, idxf, zq, zqst);
    loss_kernel<<<1, 256>>>(sc3);
}